// round 1
// baseline (speedup 1.0000x reference)
#include <cuda_runtime.h>
#include <cooperative_groups.h>
#include <math.h>

namespace cg = cooperative_groups;

constexpr int BATCH = 32;
constexpr int TLEN  = 2048;
constexpr int DIM   = 256;
constexpr float THRESH = 0.3f;
constexpr float SG_SLOPE = 4.0f;

// Precomputed x-part preactivations: P[t][b][g*256+d], gates g in {ff1, ff2, tgate}
// (tgate = Wta+Wtb merged). Includes biases. 192 MB scratch.
__device__ float g_P[(size_t)TLEN * BATCH * 768];

// ---------------------------------------------------------------------------
// Phase 1: P[m][n] = x_row(m) @ Wx + bias, m = t*32+b (65536 rows), n in [0,768)
// Only rows 0..255 of each W (the x-part of z=[x,h]) are used here.
// Tiled fp32 SIMT GEMM: 128x128 tile, BK=16, 256 threads, 8x8 microtile.
// ---------------------------------------------------------------------------
__global__ __launch_bounds__(256) void px_gemm(
    const float* __restrict__ x,
    const float* __restrict__ W1,  const float* __restrict__ b1,
    const float* __restrict__ W2,  const float* __restrict__ b2,
    const float* __restrict__ Wta, const float* __restrict__ bta,
    const float* __restrict__ Wtb, const float* __restrict__ btb)
{
    __shared__ __align__(16) float As[16][132];   // padded to dodge STS conflicts
    __shared__ __align__(16) float Bs[16][128];

    const int nt    = blockIdx.x;          // 0..5  (n-tile: 2 per gate)
    const int mt    = blockIdx.y;          // 0..511
    const int gate  = nt >> 1;
    const int ncol0 = (nt & 1) * 128;
    const float* __restrict__ Wg = (gate == 0) ? W1 : (gate == 1) ? W2 : Wta;

    const int tid = threadIdx.x;
    const int tn  = (tid & 15) * 8;
    const int tm  = (tid >> 4) * 8;
    const int m0  = mt * 128;

    float acc[8][8];
    #pragma unroll
    for (int i = 0; i < 8; i++)
        #pragma unroll
        for (int j = 0; j < 8; j++) acc[i][j] = 0.f;

    for (int k0 = 0; k0 < 256; k0 += 16) {
        // Stage A tile (transposed into As[k][m])
        #pragma unroll
        for (int i = 0; i < 2; i++) {
            int idx = tid + i * 256;          // 0..511 float4 loads
            int ml  = idx >> 2;
            int k4  = (idx & 3) * 4;
            int m   = m0 + ml;
            int b   = m & 31;
            int t   = m >> 5;
            float4 v = *(const float4*)&x[((size_t)b * TLEN + t) * 256 + k0 + k4];
            As[k4 + 0][ml] = v.x;
            As[k4 + 1][ml] = v.y;
            As[k4 + 2][ml] = v.z;
            As[k4 + 3][ml] = v.w;
        }
        // Stage B tile (Wta+Wtb folded on the fly for gate 2)
        #pragma unroll
        for (int i = 0; i < 2; i++) {
            int idx = tid + i * 256;
            int kl  = idx >> 5;
            int nl4 = (idx & 31) * 4;
            size_t off = (size_t)(k0 + kl) * 256 + ncol0 + nl4;
            float4 v = *(const float4*)&Wg[off];
            if (gate == 2) {
                float4 v2 = *(const float4*)&Wtb[off];
                v.x += v2.x; v.y += v2.y; v.z += v2.z; v.w += v2.w;
            }
            *(float4*)&Bs[kl][nl4] = v;
        }
        __syncthreads();
        #pragma unroll
        for (int k = 0; k < 16; k++) {
            float4 a0 = *(const float4*)&As[k][tm];
            float4 a1 = *(const float4*)&As[k][tm + 4];
            float4 w0 = *(const float4*)&Bs[k][tn];
            float4 w1 = *(const float4*)&Bs[k][tn + 4];
            float av[8] = {a0.x, a0.y, a0.z, a0.w, a1.x, a1.y, a1.z, a1.w};
            float bv[8] = {w0.x, w0.y, w0.z, w0.w, w1.x, w1.y, w1.z, w1.w};
            #pragma unroll
            for (int ii = 0; ii < 8; ii++)
                #pragma unroll
                for (int jj = 0; jj < 8; jj++)
                    acc[ii][jj] += av[ii] * bv[jj];
        }
        __syncthreads();
    }

    const float* __restrict__ biasA = (gate == 0) ? b1 : (gate == 1) ? b2 : bta;
    float bias[8];
    #pragma unroll
    for (int jj = 0; jj < 8; jj++) {
        float bb = biasA[ncol0 + tn + jj];
        if (gate == 2) bb += btb[ncol0 + tn + jj];
        bias[jj] = bb;
    }
    #pragma unroll
    for (int ii = 0; ii < 8; ii++) {
        size_t rowo = (size_t)(m0 + tm + ii) * 768 + (size_t)nt * 128 + tn;
        float4 o0, o1;
        o0.x = acc[ii][0] + bias[0]; o0.y = acc[ii][1] + bias[1];
        o0.z = acc[ii][2] + bias[2]; o0.w = acc[ii][3] + bias[3];
        o1.x = acc[ii][4] + bias[4]; o1.y = acc[ii][5] + bias[5];
        o1.z = acc[ii][6] + bias[6]; o1.w = acc[ii][7] + bias[7];
        *(float4*)&g_P[rowo]     = o0;
        *(float4*)&g_P[rowo + 4] = o1;
    }
}

// ---------------------------------------------------------------------------
// Phase 2: sequential CfC scan + fused PLIF.
// 16 clusters x 8 CTAs. Cluster cl handles batches {2cl, 2cl+1}.
// CTA rank r owns output dims [32r, 32r+32) for all 3 gates; its 3x256x32
// recurrent-weight slice lives in REGISTERS (64 fp32/thread x 384 threads).
// Thread (q, col): q = k-quarter (64 k each), col = gate*32 + local dim.
// h is double-buffered in SMEM; new h dims are pushed to all 8 peers via
// DSMEM; one cluster.sync per timestep.
// ---------------------------------------------------------------------------
__global__ void __launch_bounds__(384, 1) __cluster_dims__(8, 1, 1)
cfc_scan(const float* __restrict__ W1,
         const float* __restrict__ W2,
         const float* __restrict__ Wta,
         const float* __restrict__ Wtb,
         const float* __restrict__ plif_w,
         float* __restrict__ out)
{
    __shared__ __align__(16) float h_sh[2][2][DIM];   // [phase][batch][dim]
    __shared__ __align__(16) float psum[4][2][96];    // [q][batch][col]

    cg::cluster_group cluster = cg::this_cluster();
    const unsigned rank = cluster.block_rank();
    const int clu = blockIdx.x >> 3;
    const int b0  = clu * 2;

    const int tid = threadIdx.x;
    const int q   = tid / 96;        // warp-aligned: 96 cols = 3 warps per q
    const int col = tid % 96;
    const int g   = col >> 5;
    const int j   = col & 31;
    const int d   = (int)rank * 32 + j;

    // Load recurrent weights (rows 256..511 of each W). tgate folds Wta+Wtb.
    const float* __restrict__ Wg = (g == 0) ? W1 : (g == 1) ? W2 : Wta;
    float w[64];
    #pragma unroll
    for (int i = 0; i < 64; i++) {
        size_t off = (size_t)(256 + q * 64 + i) * 256 + d;
        float v = Wg[off];
        if (g == 2) v += Wtb[off];
        w[i] = v;
    }

    // Nonlinearity / PLIF threads: tid<64 -> (nb = batch 0/1, nj = local dim)
    const bool is_nl = (tid < 64);
    const int  nj = tid & 31;
    const int  nb = tid >> 5;
    const int  nd = (int)rank * 32 + nj;
    float decay = 0.f, mem = 0.f;
    if (is_nl) decay = 1.f / (1.f + expf(-plif_w[nd]));

    // h0 = 0
    for (int i = tid; i < 2 * 2 * DIM; i += 384) ((float*)h_sh)[i] = 0.f;
    __syncthreads();
    cluster.sync();

    // prefetch P for t=0
    float px0 = 0.f, px1 = 0.f, px2 = 0.f;
    if (is_nl) {
        const float* pr = g_P + ((size_t)0 * BATCH + (b0 + nb)) * 768 + nd;
        px0 = pr[0]; px1 = pr[256]; px2 = pr[512];
    }

    const size_t outB = (size_t)BATCH * TLEN * DIM;

    for (int t = 0; t < TLEN; t++) {
        const int ph = t & 1;

        // prefetch next step's P (hides DRAM latency behind the k-loop)
        float pn0 = 0.f, pn1 = 0.f, pn2 = 0.f;
        if (is_nl) {
            int tnx = (t + 1 < TLEN) ? (t + 1) : t;
            const float* pr = g_P + ((size_t)tnx * BATCH + (b0 + nb)) * 768 + nd;
            pn0 = pr[0]; pn1 = pr[256]; pn2 = pr[512];
        }

        // recurrent partial dot: this thread's 64-k slice, both batches.
        // h loads are warp-uniform -> LDS.128 broadcast.
        float acc0 = 0.f, acc1 = 0.f;
        const float4* h0v = (const float4*)&h_sh[ph][0][q * 64];
        const float4* h1v = (const float4*)&h_sh[ph][1][q * 64];
        #pragma unroll
        for (int i4 = 0; i4 < 16; i4++) {
            float4 ha = h0v[i4];
            float4 hb = h1v[i4];
            acc0 += w[4*i4+0] * ha.x; acc0 += w[4*i4+1] * ha.y;
            acc0 += w[4*i4+2] * ha.z; acc0 += w[4*i4+3] * ha.w;
            acc1 += w[4*i4+0] * hb.x; acc1 += w[4*i4+1] * hb.y;
            acc1 += w[4*i4+2] * hb.z; acc1 += w[4*i4+3] * hb.w;
        }
        psum[q][0][col] = acc0;
        psum[q][1][col] = acc1;
        __syncthreads();

        if (is_nl) {
            float s0 = psum[0][nb][nj]    + psum[1][nb][nj]    + psum[2][nb][nj]    + psum[3][nb][nj]    + px0;
            float s1 = psum[0][nb][32+nj] + psum[1][nb][32+nj] + psum[2][nb][32+nj] + psum[3][nb][32+nj] + px1;
            float s2 = psum[0][nb][64+nj] + psum[1][nb][64+nj] + psum[2][nb][64+nj] + psum[3][nb][64+nj] + px2;

            float ff1 = tanhf(s0);
            float ff2 = tanhf(s1);
            float ti  = 1.f / (1.f + expf(-s2));
            float hn  = ff1 * (1.f - ti) + ti * ff2;

            // PLIF (forward: spk == hard, emulated exactly as in reference)
            mem = decay * mem + hn;
            float hard = (mem >= THRESH) ? 1.f : 0.f;
            float soft = 1.f / (1.f + expf(-SG_SLOPE * (mem - THRESH)));
            float spk  = soft + (hard - soft);
            mem = mem - spk * THRESH;

            size_t o = ((size_t)(b0 + nb) * TLEN + t) * DIM + nd;
            out[o]            = hn;
            out[outB + o]     = spk;
            out[2 * outB + o] = mem;

            // broadcast new h dim into the next-phase buffer of all 8 CTAs
            float* loc = &h_sh[1 - ph][nb][nd];
            #pragma unroll
            for (int r = 0; r < 8; r++) {
                float* dst = cluster.map_shared_rank(loc, r);
                *dst = hn;
            }
        }
        px0 = pn0; px1 = pn1; px2 = pn2;

        // release DSMEM writes / acquire peers' writes; also guards psum reuse
        cluster.sync();
    }
}

// ---------------------------------------------------------------------------
extern "C" void kernel_launch(void* const* d_in, const int* in_sizes, int n_in,
                              void* d_out, int out_size) {
    (void)in_sizes; (void)n_in; (void)out_size;
    const float* x   = (const float*)d_in[0];
    const float* W1  = (const float*)d_in[1];
    const float* b1  = (const float*)d_in[2];
    const float* W2  = (const float*)d_in[3];
    const float* b2  = (const float*)d_in[4];
    const float* Wta = (const float*)d_in[5];
    const float* bta = (const float*)d_in[6];
    const float* Wtb = (const float*)d_in[7];
    const float* btb = (const float*)d_in[8];
    const float* plw = (const float*)d_in[9];
    float* out = (float*)d_out;

    dim3 g1(6, 512);
    px_gemm<<<g1, 256>>>(x, W1, b1, W2, b2, Wta, bta, Wtb, btb);

    cfc_scan<<<128, 384>>>(W1, W2, Wta, Wtb, plw, out);
}